// round 9
// baseline (speedup 1.0000x reference)
#include <cuda_runtime.h>
#include <math.h>

// Problem constants
#define CC    128
#define HW    4096
#define NPIX  8192
#define NCLS  4
#define KSEL  50
#define KPAD  64
#define NBIN  1024
#define MAXC  768
#define SCALE 20.6099291555566197f     // log2(e)/0.07
#define NTHR  512
#define FILT  887                      // prob >= ~0.9 prefilter bin

#define RS   132                       // padded row stride (floats) for X/P tiles
#define GSEG 8192                      // floats per class in sG (64 rows x 128, k-rot swizzle)

// smem layout (float offsets) for k_fused
#define OFF_X    0
#define OFF_P    8448
#define OFF_G    16896
#define OFF_RED  (OFF_G + NCLS * GSEG)   // 49664 (3*8*64)
#define OFF_AN   (OFF_RED + 1536)        // 51200, accN per slot
#define OFF_AA   (OFF_AN + 64)
#define OFF_INV  (OFF_AA + 64)
#define OFF_INVP (OFF_INV + 64)
#define OFF_NOM  (OFF_INVP + 64)
#define OFF_CLS  (OFF_NOM + 64)
#define OFF_PERM (OFF_CLS + 64)
#define OFF_SLOT (OFF_PERM + 64)
#define OFF_CNT  (OFF_SLOT + 64)         // 16: counts + scatter cursors
#define OFF_ST   (OFF_CNT + 16)          // 4: segment starts
#define OFF_QC   (OFF_ST + 4)            // 20: quad class
#define OFF_QB   (OFF_QC + 20)           // 20: quad base slot
#define OFF_QN   (OFF_QB + 20)           // 20: quad count
#define OFF_NQ   (OFF_QN + 20)           // 1
#define SMEM_FLOATS (OFF_NQ + 4)
#define SMEM_BYTES  (SMEM_FLOATS * 4)    // ~206.8 KB

typedef unsigned long long u64;

__device__ __forceinline__ void fma2(u64& acc, u64 a, u64 b) {
    asm("fma.rn.f32x2 %0, %1, %2, %0;" : "+l"(acc) : "l"(a), "l"(b));
}
__device__ __forceinline__ float2 upk(u64 v) {
    float2 r; asm("mov.b64 {%0,%1}, %2;" : "=f"(r.x), "=f"(r.y) : "l"(v)); return r;
}

// ---------------- device scratch ----------------
__device__ float g_Gs[NCLS][KPAD][CC];  // rows >= KSEL stay zero (never written)
__device__ float g_acc;                 // reset by last ticket each launch
__device__ unsigned int g_tick;

// ================= kernel 1: per-class top-50 selection + gather =================
__global__ __launch_bounds__(1024, 1) void k_select(const float* __restrict__ neg,
                                                    const float* __restrict__ nl) {
    __shared__ int   hist[NBIN];
    __shared__ int   schunk[32];
    __shared__ float cv[MAXC];
    __shared__ int   ci[MAXC];
    __shared__ int   ssel[KSEL];
    __shared__ int   sflag[3];           // [0]=cnt [1]=binThr [2]=total

    int s = blockIdx.x;
    int t = threadIdx.x;

    // seg / prob / bin for 8 pixels per thread (coalesced)
    int seg[8]; int bin[8]; float pvv[8];
    #pragma unroll
    for (int j = 0; j < 8; j++) {
        int px = t + j * 1024;
        int bb = px >> 12, rr = px & 4095;
        const float* pn = nl + (size_t)bb * NCLS * HW + rr;
        float l0 = pn[0], l1 = pn[HW], l2 = pn[2 * HW], l3 = pn[3 * HW];
        int amax = 0; float m = l0;
        if (l1 > m) { m = l1; amax = 1; }
        if (l2 > m) { m = l2; amax = 2; }
        if (l3 > m) { m = l3; amax = 3; }
        float sum = __expf(l0 - m) + __expf(l1 - m) + __expf(l2 - m) + __expf(l3 - m);
        float p = 1.0f / sum;
        seg[j] = amax; pvv[j] = p;
        int bb2 = (int)((p - 0.25f) * (1024.0f / 0.75f));
        bin[j] = max(0, min(NBIN - 1, bb2));
    }

    // histogram with prefilter; verified, unfiltered fallback
    int filt = FILT;
    int binThr = 0;
    for (int attempt = 0; attempt < 2; attempt++) {
        for (int i = t; i < NBIN; i += 1024) hist[i] = 0;
        __syncthreads();
        #pragma unroll
        for (int j = 0; j < 8; j++)
            if (seg[j] != s && bin[j] >= filt) atomicAdd(&hist[bin[j]], 1);
        __syncthreads();
        if (t < 32) {
            int sum = 0;
            #pragma unroll
            for (int j = 0; j < 32; j++) sum += hist[t * 32 + j];
            schunk[t] = sum;
        }
        __syncthreads();
        if (t == 0) {
            int total = 0;
            #pragma unroll
            for (int cb = 0; cb < 32; cb++) total += schunk[cb];
            int thr = filt;
            if (total >= KSEL) {
                int cum = 0;
                for (int cb = 31; cb >= 0; cb--) {
                    if (cum + schunk[cb] >= KSEL) {
                        for (int bb = cb * 32 + 31; bb >= cb * 32; bb--) {
                            cum += hist[bb];
                            if (cum >= KSEL) { thr = bb; break; }
                        }
                        break;
                    }
                    cum += schunk[cb];
                }
            }
            sflag[1] = thr;
            sflag[2] = total;
            sflag[0] = 0;
        }
        __syncthreads();
        binThr = sflag[1];
        if (sflag[2] >= KSEL) break;
        filt = 0;                        // fallback (never taken in practice)
        __syncthreads();
    }

    // collect candidates
    #pragma unroll
    for (int j = 0; j < 8; j++) {
        if (seg[j] != s && bin[j] >= binThr) {
            int p2 = atomicAdd(&sflag[0], 1);
            if (p2 < MAXC) { cv[p2] = pvv[j]; ci[p2] = t + j * 1024; }
        }
    }
    __syncthreads();
    int M = min(sflag[0], MAXC);

    // exact rank (value desc, index asc tie-break == lax.top_k)
    for (int c = t; c < M; c += 1024) {
        float v = cv[c]; int id = ci[c];
        int r = 0;
        for (int m = 0; m < M; m++) {
            float vm = cv[m];
            if (vm > v || (vm == v && ci[m] < id)) r++;
        }
        if (r < KSEL) ssel[r] = id;
    }
    __syncthreads();

    // gather + normalize + pre-scale: warp w handles rows w, w+32 (batched loads)
    {
        int w = t >> 5, lane = t & 31;
        int  kr[2] = { w, w + 32 };
        bool kval[2] = { kr[0] < KSEL, kr[1] < KSEL };
        float v[2][4];
        #pragma unroll
        for (int q = 0; q < 2; q++) {
            if (kval[q]) {
                int nn = ssel[kr[q]];
                int bb = nn >> 12, rr = nn & 4095;
                const float* p = neg + (size_t)bb * CC * HW + rr;
                #pragma unroll
                for (int j = 0; j < 4; j++)
                    v[q][j] = p[(size_t)(lane + j * 32) * HW];
            }
        }
        #pragma unroll
        for (int q = 0; q < 2; q++) {
            if (kval[q]) {
                float ss = v[q][0]*v[q][0] + v[q][1]*v[q][1]
                         + v[q][2]*v[q][2] + v[q][3]*v[q][3];
                #pragma unroll
                for (int off = 16; off; off >>= 1)
                    ss += __shfl_xor_sync(0xffffffffu, ss, off);
                float inv = SCALE / fmaxf(sqrtf(ss), 1e-12f);
                #pragma unroll
                for (int j = 0; j < 4; j++)
                    g_Gs[s][kr[q]][lane + j * 32] = v[q][j] * inv;
            }
        }
    }
}

// ================= kernel 2: fused norm + quad-GEMM + loss + ticketed output =================
__global__ __launch_bounds__(NTHR, 1) void k_fused(const float* __restrict__ inp,
                                                   const float* __restrict__ pos,
                                                   const float* __restrict__ il,
                                                   float* __restrict__ out) {
    extern __shared__ float sm[];
    float* sX    = sm + OFF_X;
    float* sP    = sm + OFF_P;
    float* sG    = sm + OFF_G;
    float* sRed  = sm + OFF_RED;
    float* sAN   = sm + OFF_AN;
    float* sAA   = sm + OFF_AA;
    float* sInv  = sm + OFF_INV;
    float* sInvP = sm + OFF_INVP;
    float* sNom  = sm + OFF_NOM;
    int*   sCls  = (int*)(sm + OFF_CLS);
    int*   sPerm = (int*)(sm + OFF_PERM);
    int*   sSlot = (int*)(sm + OFF_SLOT);
    int*   sCnt  = (int*)(sm + OFF_CNT);
    int*   sSt   = (int*)(sm + OFF_ST);
    int*   sQC   = (int*)(sm + OFF_QC);
    int*   sQB   = (int*)(sm + OFF_QB);
    int*   sQN   = (int*)(sm + OFF_QN);
    int*   sNQ   = (int*)(sm + OFF_NQ);

    int tid = threadIdx.x;
    int n   = tid & 63;
    int cg  = tid >> 6;                  // channel group 0..7
    int px0 = blockIdx.x * 64;
    int b   = px0 >> 12, rem = px0 & 4095;

    if (tid < 8) sCnt[tid] = 0;

    // ---- Phase A: x/p load + norms + class info ----
    float xv[16], pv[16];
    {
        const float* bx = inp + (size_t)b * CC * HW + rem + n;
        const float* bp = pos + (size_t)b * CC * HW + rem + n;
        float sx2 = 0.f, sp2 = 0.f, sxp = 0.f;
        #pragma unroll
        for (int j = 0; j < 16; j++) {
            int c = cg * 16 + j;
            xv[j] = bx[(size_t)c * HW];
            pv[j] = bp[(size_t)c * HW];
            sx2 += xv[j] * xv[j];
            sp2 += pv[j] * pv[j];
            sxp += xv[j] * pv[j];
        }
        sRed[(0 * 8 + cg) * 64 + n] = sx2;
        sRed[(1 * 8 + cg) * 64 + n] = sp2;
        sRed[(2 * 8 + cg) * 64 + n] = sxp;
    }
    if (tid < 64) {
        const float* pi = il + (size_t)b * NCLS * HW + rem + tid;
        float l0 = pi[0], l1 = pi[HW], l2 = pi[2 * HW], l3 = pi[3 * HW];
        int amax = 0; float m = l0;
        if (l1 > m) { m = l1; amax = 1; }
        if (l2 > m) { m = l2; amax = 2; }
        if (l3 > m) { m = l3; amax = 3; }
        sCls[tid] = amax;
    }
    __syncthreads();

    if (tid < 64) {
        float a0 = 0.f, a1 = 0.f, a2 = 0.f;
        #pragma unroll
        for (int g = 0; g < 8; g++) {
            a0 += sRed[(0 * 8 + g) * 64 + tid];
            a1 += sRed[(1 * 8 + g) * 64 + tid];
            a2 += sRed[(2 * 8 + g) * 64 + tid];
        }
        float invi = 1.0f / fmaxf(sqrtf(a0), 1e-12f);
        float invp = 1.0f / fmaxf(sqrtf(a1), 1e-12f);
        sInv[tid]  = invi;
        sInvP[tid] = invp;
        sNom[tid]  = exp2f(a2 * invi * invp * SCALE);
        atomicAdd(&sCnt[sCls[tid]], 1);
    }
    __syncthreads();

    // prefix + quad table
    if (tid == 0) {
        int acc = 0, Q = 0;
        #pragma unroll
        for (int c = 0; c < 4; c++) {
            sSt[c] = acc; sCnt[4 + c] = acc;
            int cnt = sCnt[c];
            for (int bse = 0; bse < cnt; bse += 4) {
                sQC[Q] = c; sQB[Q] = acc + bse; sQN[Q] = min(4, cnt - bse); Q++;
            }
            acc += cnt;
        }
        sNQ[0] = Q;
    }
    __syncthreads();
    if (tid < 64) {
        int pos2 = atomicAdd(&sCnt[4 + sCls[tid]], 1);
        sPerm[pos2] = tid;
        sSlot[tid]  = pos2;
    }
    __syncthreads();

    // store normalized x̂/p̂ at class-sorted rows
    {
        float invi = sInv[n], invp = sInvP[n];
        int slot = sSlot[n];
        float* dx = sX + slot * RS + cg * 16;
        float* dp = sP + slot * RS + cg * 16;
        #pragma unroll
        for (int j4 = 0; j4 < 4; j4++) {
            *(float4*)&dx[j4 * 4] = make_float4(xv[j4*4]*invi, xv[j4*4+1]*invi,
                                                xv[j4*4+2]*invi, xv[j4*4+3]*invi);
            *(float4*)&dp[j4 * 4] = make_float4(pv[j4*4]*invp, pv[j4*4+1]*invp,
                                                pv[j4*4+2]*invp, pv[j4*4+3]*invp);
        }
    }

    // ---- Phase G: load G into smem with k-rotation swizzle ----
    {
        const float4* gsrc = (const float4*)g_Gs;     // 4*64*128/4 = 8192 float4
        #pragma unroll
        for (int it = 0; it < 16; it++) {
            int f4 = tid + it * NTHR;
            int cls = f4 >> 11;                       // 2048 f4 per class
            int r   = f4 & 2047;
            int k   = r >> 5, c4p = r & 31;
            float4 v = gsrc[f4];
            int dst = cls * GSEG + k * CC + (((c4p + k) & 31) << 2);
            *(float4*)&sG[dst] = v;
        }
    }
    __syncthreads();

    // ---- Phase C: quad-GEMM. Warp owns quads of 4 same-class slots; lanes span k ----
    {
        int lane = tid & 31, w = tid >> 5;            // 16 warps
        int Q = sNQ[0];
        int k0 = 2 * lane, k1 = k0 + 1;
        bool v0 = (k0 < KSEL), v1 = (k1 < KSEL);

        for (int q = w; q < Q; q += 16) {
            int cls = sQC[q], base = sQB[q], cnt = sQN[q];
            int sq0 = base;
            int sq1 = base + min(1, cnt - 1);
            int sq2 = base + min(2, cnt - 1);
            int sq3 = base + min(3, cnt - 1);

            const float* g0row = sG + cls * GSEG + k0 * CC;
            const float* g1row = sG + cls * GSEG + k1 * CC;
            const float* x0 = sX + sq0 * RS; const float* p0 = sP + sq0 * RS;
            const float* x1 = sX + sq1 * RS; const float* p1 = sP + sq1 * RS;
            const float* x2p = sX + sq2 * RS; const float* p2p = sP + sq2 * RS;
            const float* x3 = sX + sq3 * RS; const float* p3 = sP + sq3 * RS;

            u64 aN[4][2], aA[4][2];
            #pragma unroll
            for (int j = 0; j < 4; j++) { aN[j][0]=0; aN[j][1]=0; aA[j][0]=0; aA[j][1]=0; }

            #pragma unroll 8
            for (int c4 = 0; c4 < 32; c4++) {
                ulonglong2 g0 = *(const ulonglong2*)&g0row[((c4 + k0) & 31) << 2];
                ulonglong2 g1 = *(const ulonglong2*)&g1row[((c4 + k1) & 31) << 2];
                int co = c4 << 2;
                {
                    ulonglong2 xx = *(const ulonglong2*)&x0[co];
                    ulonglong2 pp = *(const ulonglong2*)&p0[co];
                    fma2(aN[0][0], xx.x, g0.x); fma2(aN[0][0], xx.y, g0.y);
                    fma2(aN[0][1], xx.x, g1.x); fma2(aN[0][1], xx.y, g1.y);
                    fma2(aA[0][0], pp.x, g0.x); fma2(aA[0][0], pp.y, g0.y);
                    fma2(aA[0][1], pp.x, g1.x); fma2(aA[0][1], pp.y, g1.y);
                }
                {
                    ulonglong2 xx = *(const ulonglong2*)&x1[co];
                    ulonglong2 pp = *(const ulonglong2*)&p1[co];
                    fma2(aN[1][0], xx.x, g0.x); fma2(aN[1][0], xx.y, g0.y);
                    fma2(aN[1][1], xx.x, g1.x); fma2(aN[1][1], xx.y, g1.y);
                    fma2(aA[1][0], pp.x, g0.x); fma2(aA[1][0], pp.y, g0.y);
                    fma2(aA[1][1], pp.x, g1.x); fma2(aA[1][1], pp.y, g1.y);
                }
                {
                    ulonglong2 xx = *(const ulonglong2*)&x2p[co];
                    ulonglong2 pp = *(const ulonglong2*)&p2p[co];
                    fma2(aN[2][0], xx.x, g0.x); fma2(aN[2][0], xx.y, g0.y);
                    fma2(aN[2][1], xx.x, g1.x); fma2(aN[2][1], xx.y, g1.y);
                    fma2(aA[2][0], pp.x, g0.x); fma2(aA[2][0], pp.y, g0.y);
                    fma2(aA[2][1], pp.x, g1.x); fma2(aA[2][1], pp.y, g1.y);
                }
                {
                    ulonglong2 xx = *(const ulonglong2*)&x3[co];
                    ulonglong2 pp = *(const ulonglong2*)&p3[co];
                    fma2(aN[3][0], xx.x, g0.x); fma2(aN[3][0], xx.y, g0.y);
                    fma2(aN[3][1], xx.x, g1.x); fma2(aN[3][1], xx.y, g1.y);
                    fma2(aA[3][0], pp.x, g0.x); fma2(aA[3][0], pp.y, g0.y);
                    fma2(aA[3][1], pp.x, g1.x); fma2(aA[3][1], pp.y, g1.y);
                }
            }

            // per-slot exp-sums over this lane's k, butterfly over lanes = all 64 k
            #pragma unroll
            for (int j = 0; j < 4; j++) {
                float2 n0 = upk(aN[j][0]), n1 = upk(aN[j][1]);
                float2 a0 = upk(aA[j][0]), a1 = upk(aA[j][1]);
                float eN = (v0 ? exp2f(n0.x + n0.y) : 0.f) + (v1 ? exp2f(n1.x + n1.y) : 0.f);
                float eA = (v0 ? exp2f(a0.x + a0.y) : 0.f) + (v1 ? exp2f(a1.x + a1.y) : 0.f);
                #pragma unroll
                for (int off = 16; off; off >>= 1) {
                    eN += __shfl_xor_sync(0xffffffffu, eN, off);
                    eA += __shfl_xor_sync(0xffffffffu, eA, off);
                }
                if (lane == 0 && j < cnt) {
                    sAN[base + j] = eN;
                    sAA[base + j] = eA;
                }
            }
        }
    }
    __syncthreads();

    // ---- epilogue + ticketed output ----
    if (tid < 64) {
        float nom = sNom[sPerm[tid]];
        float term = logf(nom / (sAN[tid] + nom + 1e-8f))
                   + logf(nom / (sAA[tid] + nom + 1e-8f));
        #pragma unroll
        for (int off = 16; off; off >>= 1)
            term += __shfl_xor_sync(0xffffffffu, term, off);
        if ((tid & 31) == 0) atomicAdd(&g_acc, term);
    }
    __syncthreads();

    if (tid == 0) {
        __threadfence();
        unsigned int ticket = atomicAdd(&g_tick, 1u);
        if (ticket == gridDim.x - 1) {
            float v = atomicAdd(&g_acc, 0.0f);
            out[0] = -v / (float)NPIX;
            g_tick = 0u;
            g_acc  = 0.0f;              // reset for next graph replay
        }
    }
}

// ---------------- launch ----------------
extern "C" void kernel_launch(void* const* d_in, const int* in_sizes, int n_in,
                              void* d_out, int out_size) {
    const float* inp = (const float*)d_in[0];   // input    [2,128,64,64]
    const float* pos = (const float*)d_in[1];   // positive
    const float* neg = (const float*)d_in[2];   // negative
    const float* il  = (const float*)d_in[3];   // input_logits    [2,4,64,64]
    const float* nl  = (const float*)d_in[4];   // negative_logits
    float* out = (float*)d_out;

    cudaFuncSetAttribute(k_fused, cudaFuncAttributeMaxDynamicSharedMemorySize, SMEM_BYTES);

    k_select<<<NCLS, 1024>>>(neg, nl);
    k_fused<<<NPIX / 64, NTHR, SMEM_BYTES>>>(inp, pos, il, out);
}

// round 10
// speedup vs baseline: 1.0652x; 1.0652x over previous
#include <cuda_runtime.h>
#include <math.h>

// Problem constants
#define CC    128
#define HW    4096
#define NPIX  8192
#define NCLS  4
#define KSEL  50
#define KPAD  64                       // 16 k-groups x 4
#define NBIN  1024
#define MAXCAND 2048
#define SCALE 20.6099291555566197f     // log2(e)/0.07
#define NTHR  1024

#define RS 132                         // padded row stride (floats) for X/P tiles
#define CS (KPAD * CC + 4)             // class stride (floats): 8196

// smem layout (float offsets) for k_fused
#define OFF_X    0
#define OFF_P    8448
#define OFF_G    16896                       // 4 * 8196 = 32784
#define OFF_RED  (OFF_G + NCLS * CS)         // 49680 (3*16*64 = 3072)
#define OFF_EX   (OFF_RED + 3072)            // 52752 (2*16*64 = 2048)
#define OFF_INV  (OFF_EX + 2048)             // 54800
#define OFF_INVP (OFF_INV + 64)
#define OFF_NOM  (OFF_INVP + 64)
#define OFF_CLS  (OFF_NOM + 64)
#define OFF_PERM (OFF_CLS + 64)
#define OFF_SLOT (OFF_PERM + 64)
#define OFF_CNT  (OFF_SLOT + 64)             // 16
#define SMEM_FLOATS (OFF_CNT + 16)           // 55200
#define SMEM_BYTES  (SMEM_FLOATS * 4)        // 220800

typedef unsigned long long u64;

__device__ __forceinline__ void fma2(u64& acc, u64 a, u64 b) {
    asm("fma.rn.f32x2 %0, %1, %2, %0;" : "+l"(acc) : "l"(a), "l"(b));
}
__device__ __forceinline__ float2 upk(u64 v) {
    float2 r; asm("mov.b64 {%0,%1}, %2;" : "=f"(r.x), "=f"(r.y) : "l"(v)); return r;
}

// ---------------- device scratch ----------------
__device__ float g_Gs[NCLS][KPAD][CC];  // selected negatives, normalized AND pre-scaled by SCALE
__device__ float g_acc;                 // reset by last ticket each launch
__device__ unsigned int g_tick;

// ================= kernel 1: per-class top-50 selection + gather (round-5 version) =================
__global__ __launch_bounds__(1024, 1) void k_select(const float* __restrict__ neg,
                                                    const float* __restrict__ nl) {
    __shared__ int   hist[NBIN];
    __shared__ int   schunk[32];
    __shared__ float cv[MAXCAND];
    __shared__ int   ci[MAXCAND];
    __shared__ int   ssel[KSEL];
    __shared__ int   s_cnt;
    __shared__ int   s_binThr;

    int s = blockIdx.x;
    int t = threadIdx.x;

    // zero k-pad rows of this class (rows 50..63)
    for (int i = t; i < (KPAD - KSEL) * CC; i += 1024)
        (&g_Gs[s][KSEL][0])[i] = 0.0f;

    // compute seg/prob for 8 pixels per thread, straight from negative_logits
    int  seg[8];
    float pv[8];
    int  bin[8];
    #pragma unroll
    for (int j = 0; j < 8; j++) {
        int i = t + j * 1024;
        int b = i >> 12, rem = i & 4095;
        const float* pn = nl + (size_t)b * NCLS * HW + rem;
        float l0 = pn[0], l1 = pn[HW], l2 = pn[2 * HW], l3 = pn[3 * HW];
        int amax = 0; float m = l0;
        if (l1 > m) { m = l1; amax = 1; }
        if (l2 > m) { m = l2; amax = 2; }
        if (l3 > m) { m = l3; amax = 3; }
        float sum = __expf(l0 - m) + __expf(l1 - m) + __expf(l2 - m) + __expf(l3 - m);
        seg[j] = amax;
        pv[j]  = 1.0f / sum;
        int bb = (int)((pv[j] - 0.25f) * (1024.0f / 0.75f));
        bin[j] = max(0, min(NBIN - 1, bb));
    }

    for (int i = t; i < NBIN; i += 1024) hist[i] = 0;
    if (t == 0) s_cnt = 0;
    __syncthreads();

    #pragma unroll
    for (int j = 0; j < 8; j++)
        if (seg[j] != s) atomicAdd(&hist[bin[j]], 1);
    __syncthreads();

    if (t < 32) {
        int sum = 0;
        #pragma unroll
        for (int j = 0; j < 32; j++) sum += hist[t * 32 + j];
        schunk[t] = sum;
    }
    __syncthreads();
    if (t == 0) {
        int cum = 0, binThr = 0;
        for (int cb = 31; cb >= 0; cb--) {
            if (cum + schunk[cb] >= KSEL) {
                for (int bb = cb * 32 + 31; bb >= cb * 32; bb--) {
                    cum += hist[bb];
                    if (cum >= KSEL) { binThr = bb; break; }
                }
                break;
            }
            cum += schunk[cb];
        }
        s_binThr = binThr;
    }
    __syncthreads();
    int binThr = s_binThr;

    #pragma unroll
    for (int j = 0; j < 8; j++) {
        if (seg[j] != s && bin[j] >= binThr) {
            int pos = atomicAdd(&s_cnt, 1);
            if (pos < MAXCAND) { cv[pos] = pv[j]; ci[pos] = t + j * 1024; }
        }
    }
    __syncthreads();
    int M = min(s_cnt, MAXCAND);

    // exact rank (value desc, index asc tie-break == lax.top_k)
    for (int c = t; c < M; c += 1024) {
        float v = cv[c]; int id = ci[c];
        int r = 0;
        for (int m = 0; m < M; m++) {
            float vm = cv[m];
            if (vm > v || (vm == v && ci[m] < id)) r++;
        }
        if (r < KSEL) ssel[r] = id;
    }
    __syncthreads();

    // gather + normalize + pre-scale the 50 selected negatives
    {
        int w = t >> 5, lane = t & 31;
        for (int k = w; k < KSEL; k += 32) {
            int n = ssel[k];
            int b = n >> 12, rem = n & 4095;
            const float* p = neg + (size_t)b * CC * HW + rem;
            float v[4]; float ss = 0.f;
            #pragma unroll
            for (int j = 0; j < 4; j++) {
                int c = lane + j * 32;
                v[j] = p[(size_t)c * HW];
                ss += v[j] * v[j];
            }
            #pragma unroll
            for (int off = 16; off; off >>= 1) ss += __shfl_xor_sync(0xffffffffu, ss, off);
            float inv = SCALE / fmaxf(sqrtf(ss), 1e-12f);
            #pragma unroll
            for (int j = 0; j < 4; j++) {
                int c = lane + j * 32;
                g_Gs[s][k][c] = v[j] * inv;
            }
        }
    }
}

// ================= kernel 2: fused norm + class-sorted block GEMM (32 warps) =================
// 128 blocks x 1024 threads; block owns 64 consecutive pixels.
__global__ __launch_bounds__(NTHR, 1) void k_fused(const float* __restrict__ inp,
                                                   const float* __restrict__ pos,
                                                   const float* __restrict__ il,
                                                   float* __restrict__ out) {
    extern __shared__ float sm[];
    float* sX    = sm + OFF_X;
    float* sP    = sm + OFF_P;
    float* sG    = sm + OFF_G;
    float* sRed  = sm + OFF_RED;
    float* sEx   = sm + OFF_EX;
    float* sInv  = sm + OFF_INV;
    float* sInvP = sm + OFF_INVP;
    float* sNom  = sm + OFF_NOM;
    int*   sCls  = (int*)(sm + OFF_CLS);
    int*   sPerm = (int*)(sm + OFF_PERM);
    int*   sSlot = (int*)(sm + OFF_SLOT);
    int*   sCnt  = (int*)(sm + OFF_CNT);

    int tid = threadIdx.x;
    int n   = tid & 63;
    int cg  = tid >> 6;                  // channel group 0..15 (8 channels each)
    int px0 = blockIdx.x * 64;
    int b   = px0 >> 12, rem = px0 & 4095;

    if (tid < 8) sCnt[tid] = 0;

    // ---- Phase A: x/p load + partial norms ----
    float xv[8], pv[8];
    {
        const float* bx = inp + (size_t)b * CC * HW + rem + n;
        const float* bp = pos + (size_t)b * CC * HW + rem + n;
        float sx2 = 0.f, sp2 = 0.f, sxp = 0.f;
        #pragma unroll
        for (int j = 0; j < 8; j++) {
            int c = cg * 8 + j;
            xv[j] = bx[(size_t)c * HW];
            pv[j] = bp[(size_t)c * HW];
            sx2 += xv[j] * xv[j];
            sp2 += pv[j] * pv[j];
            sxp += xv[j] * pv[j];
        }
        sRed[(0 * 16 + cg) * 64 + n] = sx2;
        sRed[(1 * 16 + cg) * 64 + n] = sp2;
        sRed[(2 * 16 + cg) * 64 + n] = sxp;
    }
    if (tid < 64) {
        const float* pi = il + (size_t)b * NCLS * HW + rem + tid;
        float l0 = pi[0], l1 = pi[HW], l2 = pi[2 * HW], l3 = pi[3 * HW];
        int amax = 0; float m = l0;
        if (l1 > m) { m = l1; amax = 1; }
        if (l2 > m) { m = l2; amax = 2; }
        if (l3 > m) { m = l3; amax = 3; }
        sCls[tid] = amax;
    }
    __syncthreads();

    if (tid < 64) {
        float a0 = 0.f, a1 = 0.f, a2 = 0.f;
        #pragma unroll
        for (int g = 0; g < 16; g++) {
            a0 += sRed[(0 * 16 + g) * 64 + tid];
            a1 += sRed[(1 * 16 + g) * 64 + tid];
            a2 += sRed[(2 * 16 + g) * 64 + tid];
        }
        float invi = 1.0f / fmaxf(sqrtf(a0), 1e-12f);
        float invp = 1.0f / fmaxf(sqrtf(a1), 1e-12f);
        sInv[tid]  = invi;
        sInvP[tid] = invp;
        sNom[tid]  = exp2f(a2 * invi * invp * SCALE);
        atomicAdd(&sCnt[sCls[tid]], 1);
    }
    __syncthreads();
    if (tid == 0) {
        int acc = 0;
        #pragma unroll
        for (int c = 0; c < 4; c++) { sCnt[4 + c] = acc; acc += sCnt[c]; }
    }
    __syncthreads();
    if (tid < 64) {
        int pos2 = atomicAdd(&sCnt[4 + sCls[tid]], 1);
        sPerm[pos2] = tid;
        sSlot[tid]  = pos2;
    }
    __syncthreads();

    // store normalized x̂/p̂ at class-sorted rows
    {
        float invi = sInv[n], invp = sInvP[n];
        int slot = sSlot[n];
        float* dx = sX + slot * RS + cg * 8;
        float* dp = sP + slot * RS + cg * 8;
        *(float4*)&dx[0] = make_float4(xv[0]*invi, xv[1]*invi, xv[2]*invi, xv[3]*invi);
        *(float4*)&dx[4] = make_float4(xv[4]*invi, xv[5]*invi, xv[6]*invi, xv[7]*invi);
        *(float4*)&dp[0] = make_float4(pv[0]*invp, pv[1]*invp, pv[2]*invp, pv[3]*invp);
        *(float4*)&dp[4] = make_float4(pv[4]*invp, pv[5]*invp, pv[6]*invp, pv[7]*invp);
    }

    // ---- Phase G: load G to smem ----
    {
        const float4* gsrc = (const float4*)g_Gs;     // 4*64*128/4 = 8192 float4
        #pragma unroll
        for (int it = 0; it < 8; it++) {
            int f4 = tid + it * NTHR;
            int cls = f4 >> 11;                       // 2048 f4 per class
            int r4  = f4 & 2047;
            float4 v = gsrc[f4];
            *(float4*)&sG[cls * CS + r4 * 4] = v;
        }
    }
    __syncthreads();

    // ---- Phase C: register-tiled GEMM, 32 warps, 4 k's per thread ----
    {
        int lane = tid & 31, w = tid >> 5;           // 32 warps
        int half = w & 1, kg = w >> 1;               // kg 0..15, 4 k's each
        int slot = half * 32 + lane;
        int cls  = sCls[sPerm[slot]];
        const float* gx = sX + slot * RS;
        const float* gp = sP + slot * RS;
        const float* gg = sG + cls * CS + (kg * 4) * CC;

        u64 aN[4], aA[4];
        #pragma unroll
        for (int kk = 0; kk < 4; kk++) { aN[kk] = 0ull; aA[kk] = 0ull; }

        #pragma unroll 4
        for (int c4 = 0; c4 < 32; c4++) {
            ulonglong2 x2 = *(const ulonglong2*)&gx[c4 * 4];
            ulonglong2 p2 = *(const ulonglong2*)&gp[c4 * 4];
            #pragma unroll
            for (int kk = 0; kk < 4; kk++) {
                ulonglong2 g2 = *(const ulonglong2*)&gg[kk * CC + c4 * 4];
                fma2(aN[kk], x2.x, g2.x); fma2(aN[kk], x2.y, g2.y);
                fma2(aA[kk], p2.x, g2.x); fma2(aA[kk], p2.y, g2.y);
            }
        }

        float eN = 0.f, eA = 0.f;
        #pragma unroll
        for (int kk = 0; kk < 4; kk++) {
            if (kg * 4 + kk < KSEL) {
                float2 tn = upk(aN[kk]);
                float2 ta = upk(aA[kk]);
                eN += exp2f(tn.x + tn.y);
                eA += exp2f(ta.x + ta.y);
            }
        }
        sEx[kg * 64 + slot]        = eN;
        sEx[(16 + kg) * 64 + slot] = eA;
    }
    __syncthreads();

    // ---- epilogue + ticketed output ----
    if (tid < 64) {
        float accN = 0.f, accA = 0.f;
        #pragma unroll
        for (int g = 0; g < 16; g++) {
            accN += sEx[g * 64 + tid];
            accA += sEx[(16 + g) * 64 + tid];
        }
        float nom = sNom[sPerm[tid]];
        float term = logf(nom / (accN + nom + 1e-8f))
                   + logf(nom / (accA + nom + 1e-8f));
        #pragma unroll
        for (int off = 16; off; off >>= 1)
            term += __shfl_xor_sync(0xffffffffu, term, off);
        if ((tid & 31) == 0) atomicAdd(&g_acc, term);
    }
    __syncthreads();

    if (tid == 0) {
        __threadfence();
        unsigned int ticket = atomicAdd(&g_tick, 1u);
        if (ticket == gridDim.x - 1) {
            float v = atomicAdd(&g_acc, 0.0f);
            out[0] = -v / (float)NPIX;
            g_tick = 0u;
            g_acc  = 0.0f;              // reset for next graph replay
        }
    }
}

// ---------------- launch ----------------
extern "C" void kernel_launch(void* const* d_in, const int* in_sizes, int n_in,
                              void* d_out, int out_size) {
    const float* inp = (const float*)d_in[0];   // input    [2,128,64,64]
    const float* pos = (const float*)d_in[1];   // positive
    const float* neg = (const float*)d_in[2];   // negative
    const float* il  = (const float*)d_in[3];   // input_logits    [2,4,64,64]
    const float* nl  = (const float*)d_in[4];   // negative_logits
    float* out = (float*)d_out;

    cudaFuncSetAttribute(k_fused, cudaFuncAttributeMaxDynamicSharedMemorySize, SMEM_BYTES);

    k_select<<<NCLS, 1024>>>(neg, nl);
    k_fused<<<NPIX / 64, NTHR, SMEM_BYTES>>>(inp, pos, il, out);
}

// round 11
// speedup vs baseline: 1.1308x; 1.0615x over previous
#include <cuda_runtime.h>
#include <math.h>

// Problem constants
#define CC    128
#define HW    4096
#define NPIX  8192
#define NCLS  4
#define KSEL  50
#define KPAD  56                       // 8 k-groups x 7
#define NBIN  1024
#define MAXC  2048
#define SCALE 20.6099291555566197f     // log2(e)/0.07
#define NTHR  512
#define FILT  478                      // prob >= ~0.60 prefilter bin (very safe; fallback below)

#define RS 132                         // padded row stride (floats) for X/P tiles
#define CS (KPAD * CC + 4)             // class stride (floats): 7172

// smem layout (float offsets) for k_fused — identical to round 5
#define OFF_X    0
#define OFF_P    8448
#define OFF_G    16896
#define OFF_RED  45584                 // 3*8*64
#define OFF_EX   47120                 // 16*64
#define OFF_INV  48144
#define OFF_INVP 48208
#define OFF_NOM  48272
#define OFF_CLS  48336
#define OFF_PERM 48400
#define OFF_SLOT 48464
#define OFF_CNT  48528
#define SMEM_FLOATS 48544
#define SMEM_BYTES  (SMEM_FLOATS * 4)  // 194176

typedef unsigned long long u64;

__device__ __forceinline__ void fma2(u64& acc, u64 a, u64 b) {
    asm("fma.rn.f32x2 %0, %1, %2, %0;" : "+l"(acc) : "l"(a), "l"(b));
}
__device__ __forceinline__ float2 upk(u64 v) {
    float2 r; asm("mov.b64 {%0,%1}, %2;" : "=f"(r.x), "=f"(r.y) : "l"(v)); return r;
}

// ---------------- device scratch ----------------
__device__ float g_Gs[NCLS][KPAD][CC];  // selected negatives, normalized AND pre-scaled by SCALE
__device__ float g_acc;                 // reset by last ticket each launch
__device__ unsigned int g_tick;

// ================= kernel 1: per-class top-50 selection + gather =================
// Round-5 structure; histogram prefiltered at FILT with verified unfiltered fallback.
__global__ __launch_bounds__(1024, 1) void k_select(const float* __restrict__ neg,
                                                    const float* __restrict__ nl) {
    __shared__ int   hist[NBIN];
    __shared__ int   schunk[32];
    __shared__ float cv[MAXC];
    __shared__ int   ci[MAXC];
    __shared__ int   ssel[KSEL];
    __shared__ int   sflag[3];           // [0]=cnt [1]=binThr [2]=total

    int s = blockIdx.x;
    int t = threadIdx.x;

    // zero k-pad rows of this class (rows 50..55)
    for (int i = t; i < (KPAD - KSEL) * CC; i += 1024)
        (&g_Gs[s][KSEL][0])[i] = 0.0f;

    // compute seg/prob for 8 pixels per thread, straight from negative_logits
    int  seg[8];
    float pv[8];
    int  bin[8];
    #pragma unroll
    for (int j = 0; j < 8; j++) {
        int i = t + j * 1024;
        int b = i >> 12, rem = i & 4095;
        const float* pn = nl + (size_t)b * NCLS * HW + rem;
        float l0 = pn[0], l1 = pn[HW], l2 = pn[2 * HW], l3 = pn[3 * HW];
        int amax = 0; float m = l0;
        if (l1 > m) { m = l1; amax = 1; }
        if (l2 > m) { m = l2; amax = 2; }
        if (l3 > m) { m = l3; amax = 3; }
        float sum = __expf(l0 - m) + __expf(l1 - m) + __expf(l2 - m) + __expf(l3 - m);
        seg[j] = amax;
        pv[j]  = 1.0f / sum;
        int bb = (int)((pv[j] - 0.25f) * (1024.0f / 0.75f));
        bin[j] = max(0, min(NBIN - 1, bb));
    }

    // histogram with prefilter; verified total, unfiltered fallback if < KSEL
    int filt = FILT;
    int binThr = 0;
    for (int attempt = 0; attempt < 2; attempt++) {
        for (int i = t; i < NBIN; i += 1024) hist[i] = 0;
        __syncthreads();
        #pragma unroll
        for (int j = 0; j < 8; j++)
            if (seg[j] != s && bin[j] >= filt) atomicAdd(&hist[bin[j]], 1);
        __syncthreads();
        if (t < 32) {
            int sum = 0;
            #pragma unroll
            for (int j = 0; j < 32; j++) sum += hist[t * 32 + j];
            schunk[t] = sum;
        }
        __syncthreads();
        if (t == 0) {
            int total = 0;
            #pragma unroll
            for (int cb = 0; cb < 32; cb++) total += schunk[cb];
            int thr = filt;
            if (total >= KSEL) {
                int cum = 0;
                for (int cb = 31; cb >= 0; cb--) {
                    if (cum + schunk[cb] >= KSEL) {
                        for (int bb = cb * 32 + 31; bb >= cb * 32; bb--) {
                            cum += hist[bb];
                            if (cum >= KSEL) { thr = bb; break; }
                        }
                        break;
                    }
                    cum += schunk[cb];
                }
            }
            sflag[1] = thr;
            sflag[2] = total;
            sflag[0] = 0;
        }
        __syncthreads();
        binThr = sflag[1];
        if (sflag[2] >= KSEL) break;
        filt = 0;                        // fallback: unfiltered (never taken in practice)
        __syncthreads();
    }

    // collect candidates (everything in bin >= binThr; superset of top-50)
    #pragma unroll
    for (int j = 0; j < 8; j++) {
        if (seg[j] != s && bin[j] >= binThr) {
            int p2 = atomicAdd(&sflag[0], 1);
            if (p2 < MAXC) { cv[p2] = pv[j]; ci[p2] = t + j * 1024; }
        }
    }
    __syncthreads();
    int M = min(sflag[0], MAXC);

    // exact rank (value desc, index asc tie-break == lax.top_k)
    for (int c = t; c < M; c += 1024) {
        float v = cv[c]; int id = ci[c];
        int r = 0;
        for (int m = 0; m < M; m++) {
            float vm = cv[m];
            if (vm > v || (vm == v && ci[m] < id)) r++;
        }
        if (r < KSEL) ssel[r] = id;
    }
    __syncthreads();

    // gather + normalize + pre-scale the 50 selected negatives
    {
        int w = t >> 5, lane = t & 31;
        for (int k = w; k < KSEL; k += 32) {
            int n = ssel[k];
            int b = n >> 12, rem = n & 4095;
            const float* p = neg + (size_t)b * CC * HW + rem;
            float v[4]; float ss = 0.f;
            #pragma unroll
            for (int j = 0; j < 4; j++) {
                int c = lane + j * 32;
                v[j] = p[(size_t)c * HW];
                ss += v[j] * v[j];
            }
            #pragma unroll
            for (int off = 16; off; off >>= 1) ss += __shfl_xor_sync(0xffffffffu, ss, off);
            float inv = SCALE / fmaxf(sqrtf(ss), 1e-12f);
            #pragma unroll
            for (int j = 0; j < 4; j++) {
                int c = lane + j * 32;
                g_Gs[s][k][c] = v[j] * inv;
            }
        }
    }
}

// ================= kernel 2: fused norm + class-sorted block GEMM (round-5 verbatim) =================
// 128 blocks x 512 threads; block owns 64 consecutive pixels.
__global__ __launch_bounds__(NTHR, 1) void k_fused(const float* __restrict__ inp,
                                                   const float* __restrict__ pos,
                                                   const float* __restrict__ il,
                                                   float* __restrict__ out) {
    extern __shared__ float sm[];
    float* sX    = sm + OFF_X;
    float* sP    = sm + OFF_P;
    float* sG    = sm + OFF_G;
    float* sRed  = sm + OFF_RED;
    float* sEx   = sm + OFF_EX;
    float* sInv  = sm + OFF_INV;
    float* sInvP = sm + OFF_INVP;
    float* sNom  = sm + OFF_NOM;
    int*   sCls  = (int*)(sm + OFF_CLS);
    int*   sPerm = (int*)(sm + OFF_PERM);
    int*   sSlot = (int*)(sm + OFF_SLOT);
    int*   sCnt  = (int*)(sm + OFF_CNT);

    int tid = threadIdx.x;
    int n   = tid & 63;
    int cg  = tid >> 6;                  // 0..7 channel group
    int px0 = blockIdx.x * 64;
    int b   = px0 >> 12, rem = px0 & 4095;

    if (tid < 8) sCnt[tid] = 0;

    // ---- Phase A: load x/p to registers, partial norms; tid<64: class from input_logits ----
    float xv[16], pv[16];
    {
        const float* bx = inp + (size_t)b * CC * HW + rem + n;
        const float* bp = pos + (size_t)b * CC * HW + rem + n;
        float sx2 = 0.f, sp2 = 0.f, sxp = 0.f;
        #pragma unroll
        for (int j = 0; j < 16; j++) {
            int c = cg * 16 + j;
            xv[j] = bx[(size_t)c * HW];
            pv[j] = bp[(size_t)c * HW];
            sx2 += xv[j] * xv[j];
            sp2 += pv[j] * pv[j];
            sxp += xv[j] * pv[j];
        }
        sRed[(0 * 8 + cg) * 64 + n] = sx2;
        sRed[(1 * 8 + cg) * 64 + n] = sp2;
        sRed[(2 * 8 + cg) * 64 + n] = sxp;
    }
    if (tid < 64) {
        const float* pi = il + (size_t)b * NCLS * HW + rem + tid;
        float l0 = pi[0], l1 = pi[HW], l2 = pi[2 * HW], l3 = pi[3 * HW];
        int amax = 0; float m = l0;
        if (l1 > m) { m = l1; amax = 1; }
        if (l2 > m) { m = l2; amax = 2; }
        if (l3 > m) { m = l3; amax = 3; }
        sCls[tid] = amax;
    }
    __syncthreads();

    if (tid < 64) {
        float a0 = 0.f, a1 = 0.f, a2 = 0.f;
        #pragma unroll
        for (int g = 0; g < 8; g++) {
            a0 += sRed[(0 * 8 + g) * 64 + tid];
            a1 += sRed[(1 * 8 + g) * 64 + tid];
            a2 += sRed[(2 * 8 + g) * 64 + tid];
        }
        float invi = 1.0f / fmaxf(sqrtf(a0), 1e-12f);
        float invp = 1.0f / fmaxf(sqrtf(a1), 1e-12f);
        sInv[tid]  = invi;
        sInvP[tid] = invp;
        sNom[tid]  = exp2f(a2 * invi * invp * SCALE);
        atomicAdd(&sCnt[sCls[tid]], 1);
    }
    __syncthreads();
    if (tid == 0) {
        int acc = 0;
        #pragma unroll
        for (int c = 0; c < 4; c++) { sCnt[4 + c] = acc; acc += sCnt[c]; }
    }
    __syncthreads();
    if (tid < 64) {
        int pos2 = atomicAdd(&sCnt[4 + sCls[tid]], 1);
        sPerm[pos2] = tid;
        sSlot[tid]  = pos2;
    }
    __syncthreads();

    // store normalized x̂/p̂ at class-sorted rows
    {
        float invi = sInv[n], invp = sInvP[n];
        int slot = sSlot[n];
        float* dx = sX + slot * RS + cg * 16;
        float* dp = sP + slot * RS + cg * 16;
        #pragma unroll
        for (int j4 = 0; j4 < 4; j4++) {
            *(float4*)&dx[j4 * 4] = make_float4(xv[j4*4]*invi, xv[j4*4+1]*invi,
                                                xv[j4*4+2]*invi, xv[j4*4+3]*invi);
            *(float4*)&dp[j4 * 4] = make_float4(pv[j4*4]*invp, pv[j4*4+1]*invp,
                                                pv[j4*4+2]*invp, pv[j4*4+3]*invp);
        }
    }

    // ---- Phase G: load G to smem ----
    {
        const float4* gsrc = (const float4*)g_Gs;     // 4*56*128/4 = 7168 float4
        #pragma unroll
        for (int it = 0; it < 14; it++) {
            int f4 = tid + it * NTHR;
            int cls = f4 / 1792;
            int r4  = f4 - cls * 1792;
            float4 v = gsrc[f4];
            *(float4*)&sG[cls * CS + r4 * 4] = v;
        }
    }
    __syncthreads();

    // ---- Phase C: register-tiled GEMM ----
    {
        int lane = tid & 31, w = tid >> 5;           // 16 warps
        int half = w & 1, kg = w >> 1;               // kg 0..7, 7 k's each
        int slot = half * 32 + lane;
        int cls  = sCls[sPerm[slot]];
        const float* gx = sX + slot * RS;
        const float* gp = sP + slot * RS;
        const float* gg = sG + cls * CS + (kg * 7) * CC;

        u64 aN[7], aA[7];
        #pragma unroll
        for (int kk = 0; kk < 7; kk++) { aN[kk] = 0ull; aA[kk] = 0ull; }

        #pragma unroll 4
        for (int c4 = 0; c4 < 32; c4++) {
            ulonglong2 x2 = *(const ulonglong2*)&gx[c4 * 4];
            ulonglong2 p2 = *(const ulonglong2*)&gp[c4 * 4];
            #pragma unroll
            for (int kk = 0; kk < 7; kk++) {
                ulonglong2 g2 = *(const ulonglong2*)&gg[kk * CC + c4 * 4];
                fma2(aN[kk], x2.x, g2.x); fma2(aN[kk], x2.y, g2.y);
                fma2(aA[kk], p2.x, g2.x); fma2(aA[kk], p2.y, g2.y);
            }
        }

        float eN = 0.f, eA = 0.f;
        #pragma unroll
        for (int kk = 0; kk < 7; kk++) {
            if (kg * 7 + kk < KSEL) {
                float2 tn = upk(aN[kk]);
                float2 ta = upk(aA[kk]);
                eN += exp2f(tn.x + tn.y);
                eA += exp2f(ta.x + ta.y);
            }
        }
        sEx[kg * 64 + slot]       = eN;
        sEx[(8 + kg) * 64 + slot] = eA;
    }
    __syncthreads();

    // ---- epilogue + ticketed output ----
    if (tid < 64) {
        float accN = 0.f, accA = 0.f;
        #pragma unroll
        for (int g = 0; g < 8; g++) {
            accN += sEx[g * 64 + tid];
            accA += sEx[(8 + g) * 64 + tid];
        }
        float nom = sNom[sPerm[tid]];
        float term = logf(nom / (accN + nom + 1e-8f))
                   + logf(nom / (accA + nom + 1e-8f));
        #pragma unroll
        for (int off = 16; off; off >>= 1)
            term += __shfl_xor_sync(0xffffffffu, term, off);
        if ((tid & 31) == 0) atomicAdd(&g_acc, term);
    }
    __syncthreads();

    if (tid == 0) {
        __threadfence();
        unsigned int ticket = atomicAdd(&g_tick, 1u);
        if (ticket == gridDim.x - 1) {
            float v = atomicAdd(&g_acc, 0.0f);
            out[0] = -v / (float)NPIX;
            g_tick = 0u;
            g_acc  = 0.0f;              // reset for next graph replay
        }
    }
}

// ---------------- launch ----------------
extern "C" void kernel_launch(void* const* d_in, const int* in_sizes, int n_in,
                              void* d_out, int out_size) {
    const float* inp = (const float*)d_in[0];   // input    [2,128,64,64]
    const float* pos = (const float*)d_in[1];   // positive
    const float* neg = (const float*)d_in[2];   // negative
    const float* il  = (const float*)d_in[3];   // input_logits    [2,4,64,64]
    const float* nl  = (const float*)d_in[4];   // negative_logits
    float* out = (float*)d_out;

    cudaFuncSetAttribute(k_fused, cudaFuncAttributeMaxDynamicSharedMemorySize, SMEM_BYTES);

    k_select<<<NCLS, 1024>>>(neg, nl);
    k_fused<<<NPIX / 64, NTHR, SMEM_BYTES>>>(inp, pos, il, out);
}

// round 12
// speedup vs baseline: 1.2062x; 1.0667x over previous
#include <cuda_runtime.h>
#include <math.h>

// Problem constants
#define CC    128
#define HW    4096
#define NPIX  8192
#define NCLS  4
#define KSEL  50
#define KPAD  56                       // layout rows; only 50 used after exact trim
#define NBIN  1024
#define MAXCAND 2048
#define SCALE 20.6099291555566197f     // log2(e)/0.07
#define NTHR  512

#define RS 132                         // padded row stride (floats) for X/P tiles
#define CS (KPAD * CC + 4)             // class stride (floats): 7172

// smem layout (float offsets) for k_fused — identical to round 5
#define OFF_X    0
#define OFF_P    8448
#define OFF_G    16896
#define OFF_RED  45584                 // 3*8*64
#define OFF_EX   47120                 // 16*64
#define OFF_INV  48144
#define OFF_INVP 48208
#define OFF_NOM  48272
#define OFF_CLS  48336
#define OFF_PERM 48400
#define OFF_SLOT 48464
#define OFF_CNT  48528
#define SMEM_FLOATS 48544
#define SMEM_BYTES  (SMEM_FLOATS * 4)  // 194176

typedef unsigned long long u64;

__device__ __forceinline__ void fma2(u64& acc, u64 a, u64 b) {
    asm("fma.rn.f32x2 %0, %1, %2, %0;" : "+l"(acc) : "l"(a), "l"(b));
}
__device__ __forceinline__ float2 upk(u64 v) {
    float2 r; asm("mov.b64 {%0,%1}, %2;" : "=f"(r.x), "=f"(r.y) : "l"(v)); return r;
}

// ---------------- device scratch ----------------
__device__ float g_Gs[NCLS][KPAD][CC];  // selected negatives, normalized AND pre-scaled by SCALE
__device__ float g_acc;                 // reset by last ticket each launch
__device__ unsigned int g_tick;

// ================= kernel 1: per-class top-50 selection + gather (round-5 verbatim, minus pad zeroing) =================
__global__ __launch_bounds__(1024, 1) void k_select(const float* __restrict__ neg,
                                                    const float* __restrict__ nl) {
    __shared__ int   hist[NBIN];
    __shared__ int   schunk[32];
    __shared__ float cv[MAXCAND];
    __shared__ int   ci[MAXCAND];
    __shared__ int   ssel[KSEL];
    __shared__ int   s_cnt;
    __shared__ int   s_binThr;

    int s = blockIdx.x;
    int t = threadIdx.x;

    // compute seg/prob for 8 pixels per thread, straight from negative_logits
    int  seg[8];
    float pv[8];
    int  bin[8];
    #pragma unroll
    for (int j = 0; j < 8; j++) {
        int i = t + j * 1024;
        int b = i >> 12, rem = i & 4095;
        const float* pn = nl + (size_t)b * NCLS * HW + rem;
        float l0 = pn[0], l1 = pn[HW], l2 = pn[2 * HW], l3 = pn[3 * HW];
        int amax = 0; float m = l0;
        if (l1 > m) { m = l1; amax = 1; }
        if (l2 > m) { m = l2; amax = 2; }
        if (l3 > m) { m = l3; amax = 3; }
        float sum = __expf(l0 - m) + __expf(l1 - m) + __expf(l2 - m) + __expf(l3 - m);
        seg[j] = amax;
        pv[j]  = 1.0f / sum;
        int bb = (int)((pv[j] - 0.25f) * (1024.0f / 0.75f));
        bin[j] = max(0, min(NBIN - 1, bb));
    }

    for (int i = t; i < NBIN; i += 1024) hist[i] = 0;
    if (t == 0) s_cnt = 0;
    __syncthreads();

    #pragma unroll
    for (int j = 0; j < 8; j++)
        if (seg[j] != s) atomicAdd(&hist[bin[j]], 1);
    __syncthreads();

    if (t < 32) {
        int sum = 0;
        #pragma unroll
        for (int j = 0; j < 32; j++) sum += hist[t * 32 + j];
        schunk[t] = sum;
    }
    __syncthreads();
    if (t == 0) {
        int cum = 0, binThr = 0;
        for (int cb = 31; cb >= 0; cb--) {
            if (cum + schunk[cb] >= KSEL) {
                for (int bb = cb * 32 + 31; bb >= cb * 32; bb--) {
                    cum += hist[bb];
                    if (cum >= KSEL) { binThr = bb; break; }
                }
                break;
            }
            cum += schunk[cb];
        }
        s_binThr = binThr;
    }
    __syncthreads();
    int binThr = s_binThr;

    #pragma unroll
    for (int j = 0; j < 8; j++) {
        if (seg[j] != s && bin[j] >= binThr) {
            int pos = atomicAdd(&s_cnt, 1);
            if (pos < MAXCAND) { cv[pos] = pv[j]; ci[pos] = t + j * 1024; }
        }
    }
    __syncthreads();
    int M = min(s_cnt, MAXCAND);

    // exact rank (value desc, index asc tie-break == lax.top_k)
    for (int c = t; c < M; c += 1024) {
        float v = cv[c]; int id = ci[c];
        int r = 0;
        for (int m = 0; m < M; m++) {
            float vm = cv[m];
            if (vm > v || (vm == v && ci[m] < id)) r++;
        }
        if (r < KSEL) ssel[r] = id;
    }
    __syncthreads();

    // gather + normalize + pre-scale the 50 selected negatives
    {
        int w = t >> 5, lane = t & 31;
        for (int k = w; k < KSEL; k += 32) {
            int n = ssel[k];
            int b = n >> 12, rem = n & 4095;
            const float* p = neg + (size_t)b * CC * HW + rem;
            float v[4]; float ss = 0.f;
            #pragma unroll
            for (int j = 0; j < 4; j++) {
                int c = lane + j * 32;
                v[j] = p[(size_t)c * HW];
                ss += v[j] * v[j];
            }
            #pragma unroll
            for (int off = 16; off; off >>= 1) ss += __shfl_xor_sync(0xffffffffu, ss, off);
            float inv = SCALE / fmaxf(sqrtf(ss), 1e-12f);
            #pragma unroll
            for (int j = 0; j < 4; j++) {
                int c = lane + j * 32;
                g_Gs[s][k][c] = v[j] * inv;
            }
        }
    }
}

// ================= kernel 2: fused norm + class-sorted block GEMM =================
// Round-5 structure + cp.async G prefetch + exact k=50 trim.
__global__ __launch_bounds__(NTHR, 1) void k_fused(const float* __restrict__ inp,
                                                   const float* __restrict__ pos,
                                                   const float* __restrict__ il,
                                                   float* __restrict__ out) {
    extern __shared__ float sm[];
    float* sX    = sm + OFF_X;
    float* sP    = sm + OFF_P;
    float* sG    = sm + OFF_G;
    float* sRed  = sm + OFF_RED;
    float* sEx   = sm + OFF_EX;
    float* sInv  = sm + OFF_INV;
    float* sInvP = sm + OFF_INVP;
    float* sNom  = sm + OFF_NOM;
    int*   sCls  = (int*)(sm + OFF_CLS);
    int*   sPerm = (int*)(sm + OFF_PERM);
    int*   sSlot = (int*)(sm + OFF_SLOT);
    int*   sCnt  = (int*)(sm + OFF_CNT);

    int tid = threadIdx.x;
    int n   = tid & 63;
    int cg  = tid >> 6;                  // 0..7 channel group
    int px0 = blockIdx.x * 64;
    int b   = px0 >> 12, rem = px0 & 4095;

    if (tid < 8) sCnt[tid] = 0;

    // ---- G prefetch via cp.async: fully overlaps phase A; no register pressure ----
    {
        const float4* gsrc = (const float4*)g_Gs;     // 4*56*128/4 = 7168 float4
        #pragma unroll
        for (int it = 0; it < 14; it++) {
            int f4 = tid + it * NTHR;
            int cls = f4 / 1792;
            int r4  = f4 - cls * 1792;
            unsigned dst = (unsigned)__cvta_generic_to_shared(&sG[cls * CS + r4 * 4]);
            asm volatile("cp.async.cg.shared.global [%0], [%1], 16;\n"
                         :: "r"(dst), "l"(gsrc + f4));
        }
        asm volatile("cp.async.commit_group;\n");
    }

    // ---- Phase A: load x/p to registers, partial norms; tid<64: class from input_logits ----
    float xv[16], pv[16];
    {
        const float* bx = inp + (size_t)b * CC * HW + rem + n;
        const float* bp = pos + (size_t)b * CC * HW + rem + n;
        float sx2 = 0.f, sp2 = 0.f, sxp = 0.f;
        #pragma unroll
        for (int j = 0; j < 16; j++) {
            int c = cg * 16 + j;
            xv[j] = bx[(size_t)c * HW];
            pv[j] = bp[(size_t)c * HW];
            sx2 += xv[j] * xv[j];
            sp2 += pv[j] * pv[j];
            sxp += xv[j] * pv[j];
        }
        sRed[(0 * 8 + cg) * 64 + n] = sx2;
        sRed[(1 * 8 + cg) * 64 + n] = sp2;
        sRed[(2 * 8 + cg) * 64 + n] = sxp;
    }
    if (tid < 64) {
        const float* pi = il + (size_t)b * NCLS * HW + rem + tid;
        float l0 = pi[0], l1 = pi[HW], l2 = pi[2 * HW], l3 = pi[3 * HW];
        int amax = 0; float m = l0;
        if (l1 > m) { m = l1; amax = 1; }
        if (l2 > m) { m = l2; amax = 2; }
        if (l3 > m) { m = l3; amax = 3; }
        sCls[tid] = amax;
    }
    __syncthreads();

    if (tid < 64) {
        float a0 = 0.f, a1 = 0.f, a2 = 0.f;
        #pragma unroll
        for (int g = 0; g < 8; g++) {
            a0 += sRed[(0 * 8 + g) * 64 + tid];
            a1 += sRed[(1 * 8 + g) * 64 + tid];
            a2 += sRed[(2 * 8 + g) * 64 + tid];
        }
        float invi = 1.0f / fmaxf(sqrtf(a0), 1e-12f);
        float invp = 1.0f / fmaxf(sqrtf(a1), 1e-12f);
        sInv[tid]  = invi;
        sInvP[tid] = invp;
        sNom[tid]  = exp2f(a2 * invi * invp * SCALE);
        atomicAdd(&sCnt[sCls[tid]], 1);
    }
    __syncthreads();
    if (tid == 0) {
        int acc = 0;
        #pragma unroll
        for (int c = 0; c < 4; c++) { sCnt[4 + c] = acc; acc += sCnt[c]; }
    }
    __syncthreads();
    if (tid < 64) {
        int pos2 = atomicAdd(&sCnt[4 + sCls[tid]], 1);
        sPerm[pos2] = tid;
        sSlot[tid]  = pos2;
    }
    __syncthreads();

    // store normalized x̂/p̂ at class-sorted rows
    {
        float invi = sInv[n], invp = sInvP[n];
        int slot = sSlot[n];
        float* dx = sX + slot * RS + cg * 16;
        float* dp = sP + slot * RS + cg * 16;
        #pragma unroll
        for (int j4 = 0; j4 < 4; j4++) {
            *(float4*)&dx[j4 * 4] = make_float4(xv[j4*4]*invi, xv[j4*4+1]*invi,
                                                xv[j4*4+2]*invi, xv[j4*4+3]*invi);
            *(float4*)&dp[j4 * 4] = make_float4(pv[j4*4]*invp, pv[j4*4+1]*invp,
                                                pv[j4*4+2]*invp, pv[j4*4+3]*invp);
        }
    }

    // G must have landed; make all smem writes visible
    asm volatile("cp.async.wait_group 0;\n" ::: "memory");
    __syncthreads();

    // ---- Phase C: register-tiled GEMM, exact k=50 (kg 0..6: 7 k; kg 7: k=49 only) ----
    {
        int lane = tid & 31, w = tid >> 5;           // 16 warps
        int half = w & 1, kg = w >> 1;               // kg 0..7
        int slot = half * 32 + lane;
        int cls  = sCls[sPerm[slot]];
        const float* gx = sX + slot * RS;
        const float* gp = sP + slot * RS;
        const float* gg = sG + cls * CS + (kg * 7) * CC;

        float eN, eA;
        if (kg < 7) {
            u64 aN[7], aA[7];
            #pragma unroll
            for (int kk = 0; kk < 7; kk++) { aN[kk] = 0ull; aA[kk] = 0ull; }

            #pragma unroll 4
            for (int c4 = 0; c4 < 32; c4++) {
                ulonglong2 x2 = *(const ulonglong2*)&gx[c4 * 4];
                ulonglong2 p2 = *(const ulonglong2*)&gp[c4 * 4];
                #pragma unroll
                for (int kk = 0; kk < 7; kk++) {
                    ulonglong2 g2 = *(const ulonglong2*)&gg[kk * CC + c4 * 4];
                    fma2(aN[kk], x2.x, g2.x); fma2(aN[kk], x2.y, g2.y);
                    fma2(aA[kk], p2.x, g2.x); fma2(aA[kk], p2.y, g2.y);
                }
            }
            eN = 0.f; eA = 0.f;
            #pragma unroll
            for (int kk = 0; kk < 7; kk++) {           // k = kg*7+kk <= 48 < KSEL: no guard
                float2 tn = upk(aN[kk]);
                float2 ta = upk(aA[kk]);
                eN += exp2f(tn.x + tn.y);
                eA += exp2f(ta.x + ta.y);
            }
        } else {
            // kg == 7: single row k = 49
            u64 aN0 = 0ull, aA0 = 0ull;
            #pragma unroll 8
            for (int c4 = 0; c4 < 32; c4++) {
                ulonglong2 x2 = *(const ulonglong2*)&gx[c4 * 4];
                ulonglong2 p2 = *(const ulonglong2*)&gp[c4 * 4];
                ulonglong2 g2 = *(const ulonglong2*)&gg[c4 * 4];
                fma2(aN0, x2.x, g2.x); fma2(aN0, x2.y, g2.y);
                fma2(aA0, p2.x, g2.x); fma2(aA0, p2.y, g2.y);
            }
            float2 tn = upk(aN0), ta = upk(aA0);
            eN = exp2f(tn.x + tn.y);
            eA = exp2f(ta.x + ta.y);
        }
        sEx[kg * 64 + slot]       = eN;
        sEx[(8 + kg) * 64 + slot] = eA;
    }
    __syncthreads();

    // ---- epilogue + ticketed output ----
    if (tid < 64) {
        float accN = 0.f, accA = 0.f;
        #pragma unroll
        for (int g = 0; g < 8; g++) {
            accN += sEx[g * 64 + tid];
            accA += sEx[(8 + g) * 64 + tid];
        }
        float nom = sNom[sPerm[tid]];
        float term = logf(nom / (accN + nom + 1e-8f))
                   + logf(nom / (accA + nom + 1e-8f));
        #pragma unroll
        for (int off = 16; off; off >>= 1)
            term += __shfl_xor_sync(0xffffffffu, term, off);
        if ((tid & 31) == 0) atomicAdd(&g_acc, term);
    }
    __syncthreads();

    if (tid == 0) {
        __threadfence();
        unsigned int ticket = atomicAdd(&g_tick, 1u);
        if (ticket == gridDim.x - 1) {
            float v = atomicAdd(&g_acc, 0.0f);
            out[0] = -v / (float)NPIX;
            g_tick = 0u;
            g_acc  = 0.0f;              // reset for next graph replay
        }
    }
}

// ---------------- launch ----------------
extern "C" void kernel_launch(void* const* d_in, const int* in_sizes, int n_in,
                              void* d_out, int out_size) {
    const float* inp = (const float*)d_in[0];   // input    [2,128,64,64]
    const float* pos = (const float*)d_in[1];   // positive
    const float* neg = (const float*)d_in[2];   // negative
    const float* il  = (const float*)d_in[3];   // input_logits    [2,4,64,64]
    const float* nl  = (const float*)d_in[4];   // negative_logits
    float* out = (float*)d_out;

    cudaFuncSetAttribute(k_fused, cudaFuncAttributeMaxDynamicSharedMemorySize, SMEM_BYTES);

    k_select<<<NCLS, 1024>>>(neg, nl);
    k_fused<<<NPIX / 64, NTHR, SMEM_BYTES>>>(inp, pos, il, out);
}